// round 7
// baseline (speedup 1.0000x reference)
#include <cuda_runtime.h>
#include <cuda_bf16.h>
#include <math.h>

#define N_NODES 100000
#define IN_DIM  128
#define HID     64
#define NCLS    40
#define N_EDGES 1600000
#define CHUNK   512
#define NCHUNK  ((N_NODES + CHUNK - 1) / CHUNK)   // 196

// Scratch (__device__ globals per alloc-free rule)
__device__ float g_A[(size_t)N_NODES * HID];
__device__ float g_B[(size_t)N_NODES * HID];
__device__ int   g_cnt[N_NODES];
__device__ int   g_ptr[N_NODES + 1];
__device__ int   g_partials[NCHUNK];
__device__ int2  g_csr[N_EDGES];

// ---------------------------------------------------------------------------
// CSR construction (chain before the fused kernel)
// ---------------------------------------------------------------------------
__global__ void zero_int_kernel(int* __restrict__ p, int n) {
    int i = blockIdx.x * blockDim.x + threadIdx.x;
    if (i < n) p[i] = 0;
}

__global__ void hist_kernel(const int* __restrict__ er, int* __restrict__ cnt, int E) {
    int e = blockIdx.x * blockDim.x + threadIdx.x;
    if (e < E) atomicAdd(&cnt[er[e]], 1);
}

__global__ void chunk_reduce_kernel(const int* __restrict__ cnt, int* __restrict__ partials, int N) {
    __shared__ int s[CHUNK];
    int t = threadIdx.x;
    int i = blockIdx.x * CHUNK + t;
    s[t] = (i < N) ? cnt[i] : 0;
    __syncthreads();
    for (int off = CHUNK / 2; off > 0; off >>= 1) {
        if (t < off) s[t] += s[t + off];
        __syncthreads();
    }
    if (t == 0) partials[blockIdx.x] = s[0];
}

__global__ void block_scan_kernel(const int* __restrict__ cnt,
                                  const int* __restrict__ partials,
                                  int* __restrict__ ptr, int* __restrict__ cur,
                                  int N, int E) {
    __shared__ int s[CHUNK];
    __shared__ int p[256];
    int t = threadIdx.x;

    if (t < 256) p[t] = (t < NCHUNK) ? partials[t] : 0;
    __syncthreads();
#pragma unroll
    for (int off = 1; off < 256; off <<= 1) {
        int x = (t < 256 && t >= off) ? p[t - off] : 0;
        __syncthreads();
        if (t < 256) p[t] += x;
        __syncthreads();
    }
    const int chunkOff = (blockIdx.x == 0) ? 0 : p[blockIdx.x - 1];

    int i = blockIdx.x * CHUNK + t;
    int c = (i < N) ? cnt[i] : 0;
    s[t] = c;
    __syncthreads();
#pragma unroll
    for (int off = 1; off < CHUNK; off <<= 1) {
        int x = (t >= off) ? s[t - off] : 0;
        __syncthreads();
        s[t] += x;
        __syncthreads();
    }
    if (i < N) {
        int start = chunkOff + s[t] - c;
        ptr[i] = start;
        cur[i] = start;
        if (i == N - 1) ptr[N] = E;
    }
}

// ---------------------------------------------------------------------------
// Fused GEMM1 + scatter: role-split on blockIdx.x % 5 (1:4 interleave).
// GEMM blocks: FFMA-bound x@W1+b1.  Scatter blocks: L2-atomic CSR fill.
// ---------------------------------------------------------------------------
__global__ void fused_gemm1_scatter_kernel(
    const float* __restrict__ X, const float* __restrict__ W,
    const float* __restrict__ b, float* __restrict__ C, int N,
    const int* __restrict__ er, const int* __restrict__ ec,
    const float* __restrict__ ev,
    int* __restrict__ cur, int2* __restrict__ csr, int E)
{
    constexpr int K = IN_DIM;
    constexpr int BK = 32;
    __shared__ float Xs[64][BK + 1];
    __shared__ float Ws[BK][64];

    const int bidx = blockIdx.x;
    const int tid = threadIdx.x;

    if (bidx % 5 != 0) {
        // ---- scatter role ----
        const int sb = bidx - bidx / 5 - 1;        // 0..6249
        const int e = sb * 256 + tid;
        if (e < E) {
            int pos = atomicAdd(&cur[er[e]], 1);
            csr[pos] = make_int2(ec[e], __float_as_int(ev[e]));
        }
        return;
    }

    // ---- GEMM role ----
    const int gb = bidx / 5;                       // 0..1562
    const int tx = tid & 15;
    const int ty = tid >> 4;
    const int nodeBase = gb * 64;

    float acc[4][4];
    const float4 bv = *reinterpret_cast<const float4*>(b + tx * 4);
#pragma unroll
    for (int i = 0; i < 4; i++) {
        acc[i][0] = bv.x; acc[i][1] = bv.y; acc[i][2] = bv.z; acc[i][3] = bv.w;
    }

    for (int kc = 0; kc < K; kc += BK) {
#pragma unroll
        for (int t = 0; t < 2; t++) {
            int idx = tid + t * 256;
            int r   = idx >> 3;
            int c4  = idx & 7;
            int node = nodeBase + r;
            float4 xv = make_float4(0.f, 0.f, 0.f, 0.f);
            if (node < N)
                xv = *reinterpret_cast<const float4*>(X + (size_t)node * K + kc + c4 * 4);
            Xs[r][c4 * 4 + 0] = xv.x;
            Xs[r][c4 * 4 + 1] = xv.y;
            Xs[r][c4 * 4 + 2] = xv.z;
            Xs[r][c4 * 4 + 3] = xv.w;
        }
#pragma unroll
        for (int t = 0; t < 2; t++) {
            int idx = tid + t * 256;
            int r   = idx >> 4;
            int c4  = idx & 15;
            *reinterpret_cast<float4*>(&Ws[r][c4 * 4]) =
                *reinterpret_cast<const float4*>(W + (size_t)(kc + r) * 64 + c4 * 4);
        }
        __syncthreads();

#pragma unroll
        for (int kk = 0; kk < BK; kk++) {
            const float4 wv = *reinterpret_cast<const float4*>(&Ws[kk][tx * 4]);
            float xv[4];
#pragma unroll
            for (int i = 0; i < 4; i++) xv[i] = Xs[ty * 4 + i][kk];
#pragma unroll
            for (int i = 0; i < 4; i++) {
                acc[i][0] += xv[i] * wv.x;
                acc[i][1] += xv[i] * wv.y;
                acc[i][2] += xv[i] * wv.z;
                acc[i][3] += xv[i] * wv.w;
            }
        }
        __syncthreads();
    }

#pragma unroll
    for (int i = 0; i < 4; i++) {
        int node = nodeBase + ty * 4 + i;
        if (node < N) {
            float4 o = make_float4(acc[i][0], acc[i][1], acc[i][2], acc[i][3]);
            *reinterpret_cast<float4*>(C + (size_t)node * 64 + tx * 4) = o;
        }
    }
}

// ---------------------------------------------------------------------------
// CSR SpMM (R4): half-warp per row; lane owns one float4.
// ---------------------------------------------------------------------------
__global__ void csr_spmm_kernel(const int* __restrict__ ptr, const int2* __restrict__ csr,
                                const float* __restrict__ D, float* __restrict__ O, int N) {
    const int lane = threadIdx.x & 31;
    const int g = lane >> 4;
    const int h = lane & 15;
    const int warpId = (blockIdx.x * blockDim.x + threadIdx.x) >> 5;
    const int row = warpId * 2 + g;
    if (row >= N) return;

    const int start = ptr[row];
    const int end   = ptr[row + 1];

    float4 acc = make_float4(0.f, 0.f, 0.f, 0.f);
    int j = start;

    for (; j + 4 <= end; j += 4) {
        const int2 m0 = __ldg(&csr[j]);
        const int2 m1 = __ldg(&csr[j + 1]);
        const int2 m2 = __ldg(&csr[j + 2]);
        const int2 m3 = __ldg(&csr[j + 3]);
        const float4 a0 = *(reinterpret_cast<const float4*>(D + (size_t)m0.x * 64) + h);
        const float4 a1 = *(reinterpret_cast<const float4*>(D + (size_t)m1.x * 64) + h);
        const float4 a2 = *(reinterpret_cast<const float4*>(D + (size_t)m2.x * 64) + h);
        const float4 a3 = *(reinterpret_cast<const float4*>(D + (size_t)m3.x * 64) + h);
        const float v0 = __int_as_float(m0.y), v1 = __int_as_float(m1.y);
        const float v2 = __int_as_float(m2.y), v3 = __int_as_float(m3.y);
        acc.x += v0 * a0.x; acc.y += v0 * a0.y; acc.z += v0 * a0.z; acc.w += v0 * a0.w;
        acc.x += v1 * a1.x; acc.y += v1 * a1.y; acc.z += v1 * a1.z; acc.w += v1 * a1.w;
        acc.x += v2 * a2.x; acc.y += v2 * a2.y; acc.z += v2 * a2.z; acc.w += v2 * a2.w;
        acc.x += v3 * a3.x; acc.y += v3 * a3.y; acc.z += v3 * a3.z; acc.w += v3 * a3.w;
    }
    for (; j < end; j++) {
        const int2 m = __ldg(&csr[j]);
        const float v = __int_as_float(m.y);
        const float4 a = *(reinterpret_cast<const float4*>(D + (size_t)m.x * 64) + h);
        acc.x += v * a.x; acc.y += v * a.y; acc.z += v * a.z; acc.w += v * a.w;
    }

    *(reinterpret_cast<float4*>(O + (size_t)row * 64) + h) = acc;
}

// ---------------------------------------------------------------------------
// Tiled GEMM (R4, standalone — used for layer 2): C = act(X)@W + b
// ---------------------------------------------------------------------------
template<int K, bool RELU>
__global__ void gemm64_kernel(const float* __restrict__ X,
                              const float* __restrict__ W,
                              const float* __restrict__ b,
                              float* __restrict__ C, int N) {
    constexpr int BK = 32;
    __shared__ float Xs[64][BK + 1];
    __shared__ float Ws[BK][64];

    const int tid = threadIdx.x;
    const int tx = tid & 15;
    const int ty = tid >> 4;
    const int nodeBase = blockIdx.x * 64;

    float acc[4][4];
    const float4 bv = *reinterpret_cast<const float4*>(b + tx * 4);
#pragma unroll
    for (int i = 0; i < 4; i++) {
        acc[i][0] = bv.x; acc[i][1] = bv.y; acc[i][2] = bv.z; acc[i][3] = bv.w;
    }

    for (int kc = 0; kc < K; kc += BK) {
#pragma unroll
        for (int t = 0; t < 2; t++) {
            int idx = tid + t * 256;
            int r   = idx >> 3;
            int c4  = idx & 7;
            int node = nodeBase + r;
            float4 xv = make_float4(0.f, 0.f, 0.f, 0.f);
            if (node < N)
                xv = *reinterpret_cast<const float4*>(X + (size_t)node * K + kc + c4 * 4);
            if (RELU) {
                xv.x = fmaxf(xv.x, 0.f); xv.y = fmaxf(xv.y, 0.f);
                xv.z = fmaxf(xv.z, 0.f); xv.w = fmaxf(xv.w, 0.f);
            }
            Xs[r][c4 * 4 + 0] = xv.x;
            Xs[r][c4 * 4 + 1] = xv.y;
            Xs[r][c4 * 4 + 2] = xv.z;
            Xs[r][c4 * 4 + 3] = xv.w;
        }
#pragma unroll
        for (int t = 0; t < 2; t++) {
            int idx = tid + t * 256;
            int r   = idx >> 4;
            int c4  = idx & 15;
            *reinterpret_cast<float4*>(&Ws[r][c4 * 4]) =
                *reinterpret_cast<const float4*>(W + (size_t)(kc + r) * 64 + c4 * 4);
        }
        __syncthreads();

#pragma unroll
        for (int kk = 0; kk < BK; kk++) {
            const float4 wv = *reinterpret_cast<const float4*>(&Ws[kk][tx * 4]);
            float xv[4];
#pragma unroll
            for (int i = 0; i < 4; i++) xv[i] = Xs[ty * 4 + i][kk];
#pragma unroll
            for (int i = 0; i < 4; i++) {
                acc[i][0] += xv[i] * wv.x;
                acc[i][1] += xv[i] * wv.y;
                acc[i][2] += xv[i] * wv.z;
                acc[i][3] += xv[i] * wv.w;
            }
        }
        __syncthreads();
    }

#pragma unroll
    for (int i = 0; i < 4; i++) {
        int node = nodeBase + ty * 4 + i;
        if (node < N) {
            float4 o = make_float4(acc[i][0], acc[i][1], acc[i][2], acc[i][3]);
            *reinterpret_cast<float4*>(C + (size_t)node * 64 + tx * 4) = o;
        }
    }
}

// ---------------------------------------------------------------------------
// Classifier: out = log_softmax(H @ Wc + bc), one warp per node.
// Wc packed as float2 {class l, class 32+l} -> fewer LDS instructions.
// ---------------------------------------------------------------------------
__global__ void classifier_kernel(const float* __restrict__ H,
                                  const float* __restrict__ Wc,
                                  const float* __restrict__ bc,
                                  float* __restrict__ out, int N) {
    __shared__ float2 Wp[64][32];    // {Wc[k][l], l<8 ? Wc[k][32+l] : 0}
    __shared__ float bs[40];
    __shared__ float hs[8][64];

    const int tid  = threadIdx.x;
    const int lane = tid & 31;
    const int warp = tid >> 5;

    for (int i = tid; i < 64 * 32; i += 256) {
        int k = i >> 5, l = i & 31;
        float w0 = Wc[k * 40 + l];
        float w1 = (l < 8) ? Wc[k * 40 + 32 + l] : 0.f;
        Wp[k][l] = make_float2(w0, w1);
    }
    if (tid < 40) bs[tid] = bc[tid];
    __syncthreads();

    for (int it = 0; it < 4; it++) {
        const int node = blockIdx.x * 32 + it * 8 + warp;
        if (node < N) {
            __syncwarp();
            hs[warp][lane]      = H[(size_t)node * 64 + lane];
            hs[warp][lane + 32] = H[(size_t)node * 64 + lane + 32];
            __syncwarp();

            float v0 = bs[lane];
            float v1 = (lane < 8) ? bs[32 + lane] : 0.f;
#pragma unroll
            for (int k = 0; k < 64; k++) {
                const float h = hs[warp][k];
                const float2 w = Wp[k][lane];
                v0 += h * w.x;
                v1 += h * w.y;
            }

            float m = (lane < 8) ? fmaxf(v0, v1) : v0;
#pragma unroll
            for (int off = 16; off; off >>= 1)
                m = fmaxf(m, __shfl_xor_sync(0xffffffffu, m, off));
            float s = expf(v0 - m) + ((lane < 8) ? expf(v1 - m) : 0.f);
#pragma unroll
            for (int off = 16; off; off >>= 1)
                s += __shfl_xor_sync(0xffffffffu, s, off);
            const float lse = m + logf(s);

            out[(size_t)node * 40 + lane] = v0 - lse;
            if (lane < 8)
                out[(size_t)node * 40 + 32 + lane] = v1 - lse;
        }
    }
}

// ---------------------------------------------------------------------------
// launch (single stream)
// ---------------------------------------------------------------------------
extern "C" void kernel_launch(void* const* d_in, const int* in_sizes, int n_in,
                              void* d_out, int out_size) {
    const float* x  = (const float*)d_in[0];
    const int*   er = (const int*)  d_in[1];
    const int*   ec = (const int*)  d_in[2];
    const float* ev = (const float*)d_in[3];
    const float* W1 = (const float*)d_in[4];
    const float* b1 = (const float*)d_in[5];
    const float* W2 = (const float*)d_in[6];
    const float* b2 = (const float*)d_in[7];
    const float* Wc = (const float*)d_in[8];
    const float* bc = (const float*)d_in[9];
    float* out = (float*)d_out;

    const int N = in_sizes[0] / IN_DIM;   // 100000
    const int E = in_sizes[1];            // 1600000

    void *pA_, *pB_, *pCnt_, *pPtr_, *pPar_, *pCsr_;
    cudaGetSymbolAddress(&pA_, g_A);
    cudaGetSymbolAddress(&pB_, g_B);
    cudaGetSymbolAddress(&pCnt_, g_cnt);
    cudaGetSymbolAddress(&pPtr_, g_ptr);
    cudaGetSymbolAddress(&pPar_, g_partials);
    cudaGetSymbolAddress(&pCsr_, g_csr);
    float* A   = (float*)pA_;
    float* B   = (float*)pB_;
    int*   cnt = (int*)pCnt_;
    int*   ptr = (int*)pPtr_;
    int*   par = (int*)pPar_;
    int2*  csr = (int2*)pCsr_;

    const int gemmBlocks    = (N + 63) / 64;            // 1563
    const int eBlocks       = (E + 255) / 256;          // 6250
    const int fusedBlocks   = gemmBlocks + eBlocks;     // 7813 (1:4 interleave)
    const int spmmBlocks    = (N + 15) / 16;
    const int clsBlocks     = (N + 31) / 32;

    // --- CSR prefix chain ---
    zero_int_kernel<<<(N + 255) / 256, 256>>>(cnt, N);
    hist_kernel<<<eBlocks, 256>>>(er, cnt, E);
    chunk_reduce_kernel<<<NCHUNK, CHUNK>>>(cnt, par, N);
    block_scan_kernel<<<NCHUNK, CHUNK>>>(cnt, par, ptr, cnt /*cursor*/, N, E);

    // --- GEMM1 overlapped with scatter in one grid ---
    fused_gemm1_scatter_kernel<<<fusedBlocks, 256>>>(
        x, W1, b1, A, N, er, ec, ev, cnt, csr, E);

    // --- Layer 1 aggregate ---
    csr_spmm_kernel<<<spmmBlocks, 256>>>(ptr, csr, A, B, N);

    // --- Layer 2 (relu fused into GEMM read) ---
    gemm64_kernel<HID, true><<<gemmBlocks, 256>>>(B, W2, b2, A, N);
    csr_spmm_kernel<<<spmmBlocks, 256>>>(ptr, csr, A, B, N);

    // --- Classifier + log-softmax ---
    classifier_kernel<<<clsBlocks, 256>>>(B, Wc, bc, out, N);
}

// round 8
// speedup vs baseline: 1.4674x; 1.4674x over previous
#include <cuda_runtime.h>
#include <cuda_bf16.h>
#include <math.h>

#define N_NODES 100000
#define IN_DIM  128
#define HID     64
#define NCLS    40
#define N_EDGES 1600000
#define CHUNK   512
#define NCHUNK  ((N_NODES + CHUNK - 1) / CHUNK)   // 196

// Scratch (__device__ globals per alloc-free rule)
__device__ float g_A[(size_t)N_NODES * HID];
__device__ float g_B[(size_t)N_NODES * HID];
__device__ int   g_cnt[N_NODES];
__device__ int   g_ptr[N_NODES + 1];
__device__ int   g_partials[NCHUNK];
__device__ int2  g_csr[N_EDGES];

// ---------------------------------------------------------------------------
// CSR construction
// ---------------------------------------------------------------------------
__global__ void zero_int_kernel(int* __restrict__ p, int n) {
    int i = blockIdx.x * blockDim.x + threadIdx.x;
    if (i < n) p[i] = 0;
}

__global__ void hist_kernel(const int* __restrict__ er, int* __restrict__ cnt, int E) {
    int e = blockIdx.x * blockDim.x + threadIdx.x;
    if (e < E) atomicAdd(&cnt[er[e]], 1);
}

__global__ void chunk_reduce_kernel(const int* __restrict__ cnt, int* __restrict__ partials, int N) {
    __shared__ int s[CHUNK];
    int t = threadIdx.x;
    int i = blockIdx.x * CHUNK + t;
    s[t] = (i < N) ? cnt[i] : 0;
    __syncthreads();
    for (int off = CHUNK / 2; off > 0; off >>= 1) {
        if (t < off) s[t] += s[t + off];
        __syncthreads();
    }
    if (t == 0) partials[blockIdx.x] = s[0];
}

__global__ void block_scan_kernel(const int* __restrict__ cnt,
                                  const int* __restrict__ partials,
                                  int* __restrict__ ptr, int* __restrict__ cur,
                                  int N, int E) {
    __shared__ int s[CHUNK];
    __shared__ int p[256];
    int t = threadIdx.x;

    if (t < 256) p[t] = (t < NCHUNK) ? partials[t] : 0;
    __syncthreads();
#pragma unroll
    for (int off = 1; off < 256; off <<= 1) {
        int x = (t < 256 && t >= off) ? p[t - off] : 0;
        __syncthreads();
        if (t < 256) p[t] += x;
        __syncthreads();
    }
    const int chunkOff = (blockIdx.x == 0) ? 0 : p[blockIdx.x - 1];

    int i = blockIdx.x * CHUNK + t;
    int c = (i < N) ? cnt[i] : 0;
    s[t] = c;
    __syncthreads();
#pragma unroll
    for (int off = 1; off < CHUNK; off <<= 1) {
        int x = (t >= off) ? s[t - off] : 0;
        __syncthreads();
        s[t] += x;
        __syncthreads();
    }
    if (i < N) {
        int start = chunkOff + s[t] - c;
        ptr[i] = start;
        cur[i] = start;
        if (i == N - 1) ptr[N] = E;
    }
}

__global__ void scatter_kernel(const int* __restrict__ er, const int* __restrict__ ec,
                               const float* __restrict__ ev,
                               int* __restrict__ cur, int2* __restrict__ csr, int E) {
    int e = blockIdx.x * blockDim.x + threadIdx.x;
    if (e < E) {
        int pos = atomicAdd(&cur[er[e]], 1);
        csr[pos] = make_int2(ec[e], __float_as_int(ev[e]));
    }
}

// ---------------------------------------------------------------------------
// CSR SpMM: half-warp per row; lane owns one float4; meta via uniform LDG.64.
// ---------------------------------------------------------------------------
__global__ void csr_spmm_kernel(const int* __restrict__ ptr, const int2* __restrict__ csr,
                                const float* __restrict__ D, float* __restrict__ O, int N) {
    const int lane = threadIdx.x & 31;
    const int g = lane >> 4;
    const int h = lane & 15;
    const int warpId = (blockIdx.x * blockDim.x + threadIdx.x) >> 5;
    const int row = warpId * 2 + g;
    if (row >= N) return;

    const int start = ptr[row];
    const int end   = ptr[row + 1];

    float4 acc = make_float4(0.f, 0.f, 0.f, 0.f);
    int j = start;

    for (; j + 4 <= end; j += 4) {
        const int2 m0 = __ldg(&csr[j]);
        const int2 m1 = __ldg(&csr[j + 1]);
        const int2 m2 = __ldg(&csr[j + 2]);
        const int2 m3 = __ldg(&csr[j + 3]);
        const float4 a0 = *(reinterpret_cast<const float4*>(D + (size_t)m0.x * 64) + h);
        const float4 a1 = *(reinterpret_cast<const float4*>(D + (size_t)m1.x * 64) + h);
        const float4 a2 = *(reinterpret_cast<const float4*>(D + (size_t)m2.x * 64) + h);
        const float4 a3 = *(reinterpret_cast<const float4*>(D + (size_t)m3.x * 64) + h);
        const float v0 = __int_as_float(m0.y), v1 = __int_as_float(m1.y);
        const float v2 = __int_as_float(m2.y), v3 = __int_as_float(m3.y);
        acc.x += v0 * a0.x; acc.y += v0 * a0.y; acc.z += v0 * a0.z; acc.w += v0 * a0.w;
        acc.x += v1 * a1.x; acc.y += v1 * a1.y; acc.z += v1 * a1.z; acc.w += v1 * a1.w;
        acc.x += v2 * a2.x; acc.y += v2 * a2.y; acc.z += v2 * a2.z; acc.w += v2 * a2.w;
        acc.x += v3 * a3.x; acc.y += v3 * a3.y; acc.z += v3 * a3.z; acc.w += v3 * a3.w;
    }
    for (; j < end; j++) {
        const int2 m = __ldg(&csr[j]);
        const float v = __int_as_float(m.y);
        const float4 a = *(reinterpret_cast<const float4*>(D + (size_t)m.x * 64) + h);
        acc.x += v * a.x; acc.y += v * a.y; acc.z += v * a.z; acc.w += v * a.w;
    }

    *(reinterpret_cast<float4*>(O + (size_t)row * 64) + h) = acc;
}

// ---------------------------------------------------------------------------
// Tiled GEMM (R4, conflict-free smem): C = act(X)@W + b
// ---------------------------------------------------------------------------
template<int K, bool RELU>
__global__ void gemm64_kernel(const float* __restrict__ X,
                              const float* __restrict__ W,
                              const float* __restrict__ b,
                              float* __restrict__ C, int N) {
    constexpr int BK = 32;
    __shared__ float Xs[64][BK + 1];
    __shared__ float Ws[BK][64];

    const int tid = threadIdx.x;
    const int tx = tid & 15;
    const int ty = tid >> 4;
    const int nodeBase = blockIdx.x * 64;

    float acc[4][4];
    const float4 bv = *reinterpret_cast<const float4*>(b + tx * 4);
#pragma unroll
    for (int i = 0; i < 4; i++) {
        acc[i][0] = bv.x; acc[i][1] = bv.y; acc[i][2] = bv.z; acc[i][3] = bv.w;
    }

    for (int kc = 0; kc < K; kc += BK) {
#pragma unroll
        for (int t = 0; t < 2; t++) {
            int idx = tid + t * 256;
            int r   = idx >> 3;
            int c4  = idx & 7;
            int node = nodeBase + r;
            float4 xv = make_float4(0.f, 0.f, 0.f, 0.f);
            if (node < N)
                xv = *reinterpret_cast<const float4*>(X + (size_t)node * K + kc + c4 * 4);
            if (RELU) {
                xv.x = fmaxf(xv.x, 0.f); xv.y = fmaxf(xv.y, 0.f);
                xv.z = fmaxf(xv.z, 0.f); xv.w = fmaxf(xv.w, 0.f);
            }
            Xs[r][c4 * 4 + 0] = xv.x;
            Xs[r][c4 * 4 + 1] = xv.y;
            Xs[r][c4 * 4 + 2] = xv.z;
            Xs[r][c4 * 4 + 3] = xv.w;
        }
#pragma unroll
        for (int t = 0; t < 2; t++) {
            int idx = tid + t * 256;
            int r   = idx >> 4;
            int c4  = idx & 15;
            *reinterpret_cast<float4*>(&Ws[r][c4 * 4]) =
                *reinterpret_cast<const float4*>(W + (size_t)(kc + r) * 64 + c4 * 4);
        }
        __syncthreads();

#pragma unroll
        for (int kk = 0; kk < BK; kk++) {
            const float4 wv = *reinterpret_cast<const float4*>(&Ws[kk][tx * 4]);
            float xv[4];
#pragma unroll
            for (int i = 0; i < 4; i++) xv[i] = Xs[ty * 4 + i][kk];
#pragma unroll
            for (int i = 0; i < 4; i++) {
                acc[i][0] += xv[i] * wv.x;
                acc[i][1] += xv[i] * wv.y;
                acc[i][2] += xv[i] * wv.z;
                acc[i][3] += xv[i] * wv.w;
            }
        }
        __syncthreads();
    }

#pragma unroll
    for (int i = 0; i < 4; i++) {
        int node = nodeBase + ty * 4 + i;
        if (node < N) {
            float4 o = make_float4(acc[i][0], acc[i][1], acc[i][2], acc[i][3]);
            *reinterpret_cast<float4*>(C + (size_t)node * 64 + tx * 4) = o;
        }
    }
}

// ---------------------------------------------------------------------------
// Classifier: out = log_softmax(H @ Wc + bc), one warp per node.
// Wc packed as float2 {class l, class 32+l} (validated in R7, bit-identical).
// ---------------------------------------------------------------------------
__global__ void classifier_kernel(const float* __restrict__ H,
                                  const float* __restrict__ Wc,
                                  const float* __restrict__ bc,
                                  float* __restrict__ out, int N) {
    __shared__ float2 Wp[64][32];
    __shared__ float bs[40];
    __shared__ float hs[8][64];

    const int tid  = threadIdx.x;
    const int lane = tid & 31;
    const int warp = tid >> 5;

    for (int i = tid; i < 64 * 32; i += 256) {
        int k = i >> 5, l = i & 31;
        float w0 = Wc[k * 40 + l];
        float w1 = (l < 8) ? Wc[k * 40 + 32 + l] : 0.f;
        Wp[k][l] = make_float2(w0, w1);
    }
    if (tid < 40) bs[tid] = bc[tid];
    __syncthreads();

    for (int it = 0; it < 4; it++) {
        const int node = blockIdx.x * 32 + it * 8 + warp;
        if (node < N) {
            __syncwarp();
            hs[warp][lane]      = H[(size_t)node * 64 + lane];
            hs[warp][lane + 32] = H[(size_t)node * 64 + lane + 32];
            __syncwarp();

            float v0 = bs[lane];
            float v1 = (lane < 8) ? bs[32 + lane] : 0.f;
#pragma unroll
            for (int k = 0; k < 64; k++) {
                const float h = hs[warp][k];
                const float2 w = Wp[k][lane];
                v0 += h * w.x;
                v1 += h * w.y;
            }

            float m = (lane < 8) ? fmaxf(v0, v1) : v0;
#pragma unroll
            for (int off = 16; off; off >>= 1)
                m = fmaxf(m, __shfl_xor_sync(0xffffffffu, m, off));
            float s = expf(v0 - m) + ((lane < 8) ? expf(v1 - m) : 0.f);
#pragma unroll
            for (int off = 16; off; off >>= 1)
                s += __shfl_xor_sync(0xffffffffu, s, off);
            const float lse = m + logf(s);

            out[(size_t)node * 40 + lane] = v0 - lse;
            if (lane < 8)
                out[(size_t)node * 40 + 32 + lane] = v1 - lse;
        }
    }
}

// ---------------------------------------------------------------------------
// launch (single stream, R4 structure)
// ---------------------------------------------------------------------------
extern "C" void kernel_launch(void* const* d_in, const int* in_sizes, int n_in,
                              void* d_out, int out_size) {
    const float* x  = (const float*)d_in[0];
    const int*   er = (const int*)  d_in[1];
    const int*   ec = (const int*)  d_in[2];
    const float* ev = (const float*)d_in[3];
    const float* W1 = (const float*)d_in[4];
    const float* b1 = (const float*)d_in[5];
    const float* W2 = (const float*)d_in[6];
    const float* b2 = (const float*)d_in[7];
    const float* Wc = (const float*)d_in[8];
    const float* bc = (const float*)d_in[9];
    float* out = (float*)d_out;

    const int N = in_sizes[0] / IN_DIM;   // 100000
    const int E = in_sizes[1];            // 1600000

    void *pA_, *pB_, *pCnt_, *pPtr_, *pPar_, *pCsr_;
    cudaGetSymbolAddress(&pA_, g_A);
    cudaGetSymbolAddress(&pB_, g_B);
    cudaGetSymbolAddress(&pCnt_, g_cnt);
    cudaGetSymbolAddress(&pPtr_, g_ptr);
    cudaGetSymbolAddress(&pPar_, g_partials);
    cudaGetSymbolAddress(&pCsr_, g_csr);
    float* A   = (float*)pA_;
    float* B   = (float*)pB_;
    int*   cnt = (int*)pCnt_;
    int*   ptr = (int*)pPtr_;
    int*   par = (int*)pPar_;
    int2*  csr = (int2*)pCsr_;

    const int gemmBlocks = (N + 63) / 64;
    const int eBlocks    = (E + 255) / 256;
    const int spmmBlocks = (N + 15) / 16;
    const int clsBlocks  = (N + 31) / 32;

    // --- CSR build ---
    zero_int_kernel<<<(N + 255) / 256, 256>>>(cnt, N);
    hist_kernel<<<eBlocks, 256>>>(er, cnt, E);
    chunk_reduce_kernel<<<NCHUNK, CHUNK>>>(cnt, par, N);
    block_scan_kernel<<<NCHUNK, CHUNK>>>(cnt, par, ptr, cnt /*cursor*/, N, E);
    scatter_kernel<<<eBlocks, 256>>>(er, ec, ev, cnt, csr, E);

    // --- Layer 1 ---
    gemm64_kernel<IN_DIM, false><<<gemmBlocks, 256>>>(x, W1, b1, A, N);
    csr_spmm_kernel<<<spmmBlocks, 256>>>(ptr, csr, A, B, N);

    // --- Layer 2 (relu fused into GEMM read) ---
    gemm64_kernel<HID, true><<<gemmBlocks, 256>>>(B, W2, b2, A, N);
    csr_spmm_kernel<<<spmmBlocks, 256>>>(ptr, csr, A, B, N);

    // --- Classifier + log-softmax ---
    classifier_kernel<<<clsBlocks, 256>>>(B, Wc, bc, out, N);
}